// round 16
// baseline (speedup 1.0000x reference)
#include <cuda_runtime.h>
#include <cuda_bf16.h>
#include <cstdint>
#include <stdint.h>
#include <math.h>

#define HW   256
#define PIX  65536
#define NB   8
#define NC   64
#define BP   72    // bf16 smem pitch
#define FP   65    // fp32 smem pitch

// ---- scratch ----
__device__ float g_gap[NB * NC];
__device__ float g_gate[NB * NC];
__device__ float g_wvo[4096];   // out_w @ v_w
__device__ float g_bvo[64];     // out_w @ v_b + out_b
__device__ float g_m[4096];     // B[n][k] = sum_o Wq[o][k] * Wk[o][n]
__device__ float g_wv[64];      // w_v[c] = sum_o bq[o] * Wk[o][c]

// fragment-packed bf16 weights
__device__ __align__(16) uint2 g_wmf[1024];
__device__ __align__(16) uint2 g_wvof[1024];
__device__ __align__(16) uint2 g_f1f[1024];
__device__ __align__(16) uint2 g_f2f[1024];
__device__ __align__(16) uint2 g_wvv[128];      // v-vector frag (row 0 only)
__device__ __align__(16) uint2 g_w1f[9 * 512];
__device__ __align__(16) uint2 g_w2f[512];

// ============================================================
__device__ __forceinline__ void mma_bf16(float acc[4], uint32_t a0, uint32_t a1,
                                         uint32_t a2, uint32_t a3,
                                         uint32_t b0, uint32_t b1) {
    asm volatile(
        "mma.sync.aligned.m16n8k16.row.col.f32.bf16.bf16.f32 "
        "{%0,%1,%2,%3},{%4,%5,%6,%7},{%8,%9},{%0,%1,%2,%3};"
        : "+f"(acc[0]), "+f"(acc[1]), "+f"(acc[2]), "+f"(acc[3])
        : "r"(a0), "r"(a1), "r"(a2), "r"(a3), "r"(b0), "r"(b1));
}

__device__ __forceinline__ uint32_t pk(float x, float y) {
    __nv_bfloat162 h = __floats2bfloat162_rn(x, y);
    return *(uint32_t*)&h;
}

__device__ __forceinline__ uint32_t s2u(const void* p) {
    return (uint32_t)__cvta_generic_to_shared(p);
}

__device__ __forceinline__ void ldsm4(uint32_t r[4], uint32_t a) {
    asm volatile("ldmatrix.sync.aligned.m8n8.x4.shared.b16 {%0,%1,%2,%3}, [%4];"
                 : "=r"(r[0]), "=r"(r[1]), "=r"(r[2]), "=r"(r[3]) : "r"(a));
}

__device__ __forceinline__ void lda4(uint32_t af[4][4], const __nv_bfloat16* A, int lane) {
    int lr = lane & 7, quad = lane >> 3;
    const __nv_bfloat16* p = A + (lr + (quad & 1) * 8) * BP + (quad >> 1) * 8;
    #pragma unroll
    for (int kt = 0; kt < 4; kt++) ldsm4(af[kt], s2u(p + 16 * kt));
}

// A-frags = window tokens gathered from the 10x18 halo tile
__device__ __forceinline__ void lda4_win(uint32_t af[4][4], const __nv_bfloat16* halo,
                                         int wx2, int tb, int lane) {
    int lr = lane & 7, quad = lane >> 3;
    int token = tb + lr + (quad & 1) * 8;
    int ty = token >> 3, tx = token & 7;
    const __nv_bfloat16* p = halo + ((1 + ty) * 18 + 1 + wx2 * 8 + tx) * BP
                           + (quad >> 1) * 8;
    #pragma unroll
    for (int kt = 0; kt < 4; kt++) ldsm4(af[kt], s2u(p + 16 * kt));
}

__device__ __forceinline__ void gemm8_gf(const uint32_t af[4][4],
                                         const uint2* __restrict__ Bf,
                                         int lane, float acc[8][4]) {
    #pragma unroll
    for (int kt = 0; kt < 4; kt++)
        #pragma unroll
        for (int nt = 0; nt < 8; nt++) {
            uint2 b = __ldg(&Bf[(kt * 8 + nt) * 32 + lane]);
            mma_bf16(acc[nt], af[kt][0], af[kt][1], af[kt][2], af[kt][3], b.x, b.y);
        }
}

__device__ __forceinline__ void chain8_s(const float ca[8][4],
                                         const __nv_bfloat16* __restrict__ B,
                                         int lane, float acc[8][4]) {
    int lr = lane & 7, quad = lane >> 3;
    #pragma unroll
    for (int kt = 0; kt < 4; kt++) {
        uint32_t a0 = pk(ca[2 * kt][0], ca[2 * kt][1]);
        uint32_t a1 = pk(ca[2 * kt][2], ca[2 * kt][3]);
        uint32_t a2 = pk(ca[2 * kt + 1][0], ca[2 * kt + 1][1]);
        uint32_t a3 = pk(ca[2 * kt + 1][2], ca[2 * kt + 1][3]);
        #pragma unroll
        for (int p = 0; p < 4; p++) {
            uint32_t bf[4];
            ldsm4(bf, s2u(B + (16 * p + lr + (quad >> 1) * 8) * BP
                          + (quad & 1) * 8 + 16 * kt));
            mma_bf16(acc[2 * p],     a0, a1, a2, a3, bf[0], bf[1]);
            mma_bf16(acc[2 * p + 1], a0, a1, a2, a3, bf[2], bf[3]);
        }
    }
}

// scores chain: B rows are window tokens straight from the halo
__device__ __forceinline__ void chainS_win(const float ca[8][4],
                                           const __nv_bfloat16* __restrict__ halo,
                                           int wx2, int lane, float acc[8][4]) {
    int lr = lane & 7, quad = lane >> 3;
    int half8 = (quad >> 1) * 8, koff = (quad & 1) * 8;
    #pragma unroll
    for (int kt = 0; kt < 4; kt++) {
        uint32_t a0 = pk(ca[2 * kt][0], ca[2 * kt][1]);
        uint32_t a1 = pk(ca[2 * kt][2], ca[2 * kt][3]);
        uint32_t a2 = pk(ca[2 * kt + 1][0], ca[2 * kt + 1][1]);
        uint32_t a3 = pk(ca[2 * kt + 1][2], ca[2 * kt + 1][3]);
        #pragma unroll
        for (int p = 0; p < 4; p++) {
            int tok = 16 * p + lr + half8;
            int ty = tok >> 3, tx = tok & 7;
            uint32_t bf[4];
            ldsm4(bf, s2u(halo + ((1 + ty) * 18 + 1 + wx2 * 8 + tx) * BP
                          + koff + 16 * kt));
            mma_bf16(acc[2 * p],     a0, a1, a2, a3, bf[0], bf[1]);
            mma_bf16(acc[2 * p + 1], a0, a1, a2, a3, bf[2], bf[3]);
        }
    }
}

__device__ __forceinline__ void chain8_g(const float ca[8][4],
                                         const uint2* __restrict__ Bf,
                                         int lane, float acc[8][4]) {
    #pragma unroll
    for (int kt = 0; kt < 4; kt++) {
        uint32_t a0 = pk(ca[2 * kt][0], ca[2 * kt][1]);
        uint32_t a1 = pk(ca[2 * kt][2], ca[2 * kt][3]);
        uint32_t a2 = pk(ca[2 * kt + 1][0], ca[2 * kt + 1][1]);
        uint32_t a3 = pk(ca[2 * kt + 1][2], ca[2 * kt + 1][3]);
        #pragma unroll
        for (int nt = 0; nt < 8; nt++) {
            uint2 b = __ldg(&Bf[(kt * 8 + nt) * 32 + lane]);
            mma_bf16(acc[nt], a0, a1, a2, a3, b.x, b.y);
        }
    }
}

__device__ __forceinline__ void bias8(float acc[8][4], const float* __restrict__ b, int lane) {
    int tg = lane & 3;
    #pragma unroll
    for (int nt = 0; nt < 8; nt++) {
        float b0 = __ldg(b + 8 * nt + 2 * tg);
        float b1 = __ldg(b + 8 * nt + 2 * tg + 1);
        acc[nt][0] = b0; acc[nt][1] = b1; acc[nt][2] = b0; acc[nt][3] = b1;
    }
}

__device__ __forceinline__ void zero8(float acc[8][4]) {
    #pragma unroll
    for (int nt = 0; nt < 8; nt++)
        #pragma unroll
        for (int i = 0; i < 4; i++) acc[nt][i] = 0.f;
}

// ============================================================
// K-1: folds. wvo = out_w@v_w; bvo = out_w@v_b + out_b;
// M_B[n][k] = sum_o Wq[o][k]*Wk[o][n]; w_v = Wk^T @ bq.
// Also zero g_gap.
// ============================================================
__global__ void k_fold(const float* __restrict__ qk_w, const float* __restrict__ qk_b,
                       const float* __restrict__ out_w, const float* __restrict__ v_w,
                       const float* __restrict__ v_b, const float* __restrict__ out_b) {
    int idx = blockIdx.x * 256 + threadIdx.x;
    if (idx < 512) g_gap[idx] = 0.f;
    int o = idx >> 6, i = idx & 63;
    float s = 0.f, m = 0.f;
    #pragma unroll 8
    for (int c = 0; c < 64; c++) {
        s += out_w[o * 64 + c] * v_w[c * 64 + i];
        m += qk_w[c * 64 + i] * qk_w[4096 + c * 64 + o];
    }
    g_wvo[idx] = s;
    g_m[idx] = m;       // B[n=o][k=i]
    if (i == 0) {
        float bb = out_b[o], wv = 0.f;
        for (int c = 0; c < 64; c++) {
            bb += out_w[o * 64 + c] * v_b[c];
            wv += qk_b[c] * qk_w[4096 + c * 64 + o];
        }
        g_bvo[o] = bb;
        g_wv[o] = wv;
    }
}

// ============================================================
// K0: combined weight-pack (blocks 0..23) + GAP (blocks 24..)
// ============================================================
__global__ void k_prep_gap(const float* __restrict__ fc1_w, const float* __restrict__ fc2_w,
                           const float* __restrict__ ms1_w, const float* __restrict__ ms2_w,
                           const float* __restrict__ x) {
    if (blockIdx.x >= 24) {
        int gb = blockIdx.x - 24;
        int bc = gb >> 2, part = gb & 3;
        const float4* p = (const float4*)(x + (size_t)bc * PIX) + part * 4096;
        float s = 0.f;
        #pragma unroll 4
        for (int i = threadIdx.x; i < 4096; i += 256) {
            float4 v = __ldg(&p[i]);
            s += v.x + v.y + v.z + v.w;
        }
        #pragma unroll
        for (int st = 16; st > 0; st >>= 1) s += __shfl_xor_sync(0xffffffffu, s, st);
        __shared__ float red[8];
        if ((threadIdx.x & 31) == 0) red[threadIdx.x >> 5] = s;
        __syncthreads();
        if (threadIdx.x == 0) {
            float t = 0.f;
            #pragma unroll
            for (int i = 0; i < 8; i++) t += red[i];
            atomicAdd(&g_gap[bc], t * (1.f / PIX));
        }
        return;
    }
    int n = 24 * 256;
    int t0 = blockIdx.x * 256 + threadIdx.x;
    for (int idx = t0; idx < 1024; idx += n) {
        int kt = idx >> 8, r = idx & 255;
        int nt = r >> 5, lane = r & 31;
        int g = lane >> 2, tg = lane & 3;
        int row = 8 * nt + g, col = 2 * tg + 16 * kt;
        #define PACK64(W) make_uint2(pk((W)[row * 64 + col], (W)[row * 64 + col + 1]), \
                                     pk((W)[row * 64 + col + 8], (W)[row * 64 + col + 9]))
        g_wmf[idx]  = PACK64(g_m);
        g_wvof[idx] = PACK64(g_wvo);
        g_f1f[idx]  = PACK64(fc1_w);
        g_f2f[idx]  = PACK64(fc2_w);
        #undef PACK64
    }
    for (int idx = t0; idx < 128; idx += n) {   // v-vector frag: row 0 only
        int kt = idx >> 5, lane = idx & 31;
        int g = lane >> 2, tg = lane & 3;
        int col = 2 * tg + 16 * kt;
        uint2 u = make_uint2(0u, 0u);
        if (g == 0) {
            u.x = pk(g_wv[col], g_wv[col + 1]);
            u.y = pk(g_wv[col + 8], g_wv[col + 9]);
        }
        g_wvv[idx] = u;
    }
    for (int idx = t0; idx < 9 * 512; idx += n) {
        int tap = idx >> 9, r = idx & 511;
        int kt = r >> 7, r2 = r & 127;
        int nt = r2 >> 5, lane = r2 & 31;
        int g = lane >> 2, tg = lane & 3;
        int row = 8 * nt + g, col = 2 * tg + 16 * kt;
        uint2 u;
        u.x = pk(ms1_w[(row * 64 + col) * 9 + tap],     ms1_w[(row * 64 + col + 1) * 9 + tap]);
        u.y = pk(ms1_w[(row * 64 + col + 8) * 9 + tap], ms1_w[(row * 64 + col + 9) * 9 + tap]);
        g_w1f[idx] = u;
    }
    for (int idx = t0; idx < 512; idx += n) {
        int kt = idx >> 8, r = idx & 255;
        int nt = r >> 5, lane = r & 31;
        int g = lane >> 2, tg = lane & 3;
        int row = 8 * nt + g, col = 2 * tg + 16 * kt;
        uint2 u;
        u.x = pk(ms2_w[row * 32 + col],     ms2_w[row * 32 + col + 1]);
        u.y = pk(ms2_w[row * 32 + col + 8], ms2_w[row * 32 + col + 9]);
        g_w2f[idx] = u;
    }
}

__global__ void k_gate(const float* __restrict__ se1_w, const float* __restrict__ se1_b,
                       const float* __restrict__ se2_w, const float* __restrict__ se2_b) {
    __shared__ float se[NB][4];
    int tid = threadIdx.x;
    if (tid < 32) {
        int b = tid >> 2, j = tid & 3;
        float s = se1_b[j];
        for (int c = 0; c < NC; c++) s += g_gap[b * NC + c] * se1_w[j * NC + c];
        se[b][j] = fmaxf(s, 0.f);
    }
    __syncthreads();
    int b = tid >> 6, o = tid & 63;
    float s = se2_b[o];
    #pragma unroll
    for (int j = 0; j < 4; j++) s += se[b][j] * se2_w[o * 4 + j];
    g_gate[tid] = 1.f / (1.f + __expf(-s));
}

// ============================================================
// MEGA kernel, 8x16 tile per CTA, 256 threads, 2 CTAs/SM.
// Attention via folded scores: S = (x M) x^T + v_s  (softmax-equivalent)
// ============================================================
__device__ __forceinline__ float gelu_f(float v) {
    float u = 0.7978845608028654f * (v + 0.044715f * v * v * v);
    return v / (1.f + __expf(-2.f * u));
}

__global__ void __launch_bounds__(256, 2) k_mega(
        const float* __restrict__ x,
        const float* __restrict__ ms1_b, const float* __restrict__ ms2_b,
        const float* __restrict__ ln_g, const float* __restrict__ ln_b,
        const float* __restrict__ fc1_b, const float* __restrict__ fc2_b,
        float* __restrict__ out) {
    extern __shared__ char smc[];
    __nv_bfloat16* halo  = (__nv_bfloat16*)smc;            // [180][BP] = 25920B
    float*         stage = (float*)smc;                    // [128][FP] = 33280B (aliases halo)
    __nv_bfloat16* vT    = (__nv_bfloat16*)(smc + 33280);  // [2][64][BP] = 18432B
    float*         vsm   = (float*)(smc + 51712);          // [128] = 512B
    __nv_bfloat16* attnA = (__nv_bfloat16*)(smc + 52224);  // [128][BP] = 18432B
    __nv_bfloat16* tn    = attnA;                           // aliased after residual

    int tid = threadIdx.x, lane = tid & 31, wid = tid >> 5;
    int g = lane >> 2, tg = lane & 3;
    int lr = lane & 7, quad = lane >> 3;
    int b = blockIdx.z;
    int gy0 = blockIdx.y << 3, gx0 = blockIdx.x << 4;

    // ---- halo load: 10 rows x 18 cols x 64 ch ----
    for (int idx = tid; idx < 11520; idx += 256) {
        int c = idx / 180, r = idx - c * 180;
        int hy = r / 18, hx = r - hy * 18;
        int gy = gy0 + hy - 1, gx = gx0 + hx - 1;
        float v = 0.f;
        if (gy >= 0 && gy < HW && gx >= 0 && gx < HW)
            v = x[((size_t)(b * NC + c)) * PIX + (size_t)gy * HW + gx];
        halo[r * BP + c] = __float2bfloat16(v);
    }
    __syncthreads();

    // ---- attention: warp w -> window w>>2 (wx2), quarter w&3 ----
    int wx2 = wid >> 2, q4 = wid & 3;
    int tb = q4 * 16;
    __nv_bfloat16* vw = vT + wx2 * 64 * BP;

    {   // gated VO proj + v-vector
        uint32_t af[4][4];
        lda4_win(af, halo, wx2, tb, lane);

        float acc[8][4];
        bias8(acc, g_bvo, lane);
        gemm8_gf(af, g_wvof, lane, acc);
        int tI = tb + g;
        #pragma unroll
        for (int nt = 0; nt < 8; nt++) {
            int ch = 8 * nt + 2 * tg;
            float ga0 = __ldg(&g_gate[b * NC + ch]);
            float ga1 = __ldg(&g_gate[b * NC + ch + 1]);
            vw[ch * BP + tI]           = __float2bfloat16(acc[nt][0] * ga0);
            vw[(ch + 1) * BP + tI]     = __float2bfloat16(acc[nt][1] * ga1);
            vw[ch * BP + tI + 8]       = __float2bfloat16(acc[nt][2] * ga0);
            vw[(ch + 1) * BP + tI + 8] = __float2bfloat16(acc[nt][3] * ga1);
        }

        float vac[4] = {0.f, 0.f, 0.f, 0.f};
        #pragma unroll
        for (int kt = 0; kt < 4; kt++) {
            uint2 bv = __ldg(&g_wvv[kt * 32 + lane]);
            mma_bf16(vac, af[kt][0], af[kt][1], af[kt][2], af[kt][3], bv.x, bv.y);
        }
        if (tg == 0) {
            vsm[wx2 * 64 + tb + g]     = vac[0];
            vsm[wx2 * 64 + tb + 8 + g] = vac[2];
        }
    }
    __syncthreads();

    {   // y = x M, scores = y x^T + v_s, softmax, P@u -> attnA
        uint32_t af[4][4];
        lda4_win(af, halo, wx2, tb, lane);
        float yac[8][4];
        zero8(yac);
        gemm8_gf(af, g_wmf, lane, yac);

        float sac[8][4];
        zero8(sac);
        chainS_win(yac, halo, wx2, lane, sac);
        {
            const float* vb = vsm + wx2 * 64;
            #pragma unroll
            for (int nt = 0; nt < 8; nt++) {
                float v0 = vb[8 * nt + 2 * tg], v1 = vb[8 * nt + 2 * tg + 1];
                sac[nt][0] += v0; sac[nt][1] += v1;
                sac[nt][2] += v0; sac[nt][3] += v1;
            }
        }

        float mx0 = -1e30f, mx1 = -1e30f;
        #pragma unroll
        for (int nt = 0; nt < 8; nt++) {
            mx0 = fmaxf(mx0, fmaxf(sac[nt][0], sac[nt][1]));
            mx1 = fmaxf(mx1, fmaxf(sac[nt][2], sac[nt][3]));
        }
        mx0 = fmaxf(mx0, __shfl_xor_sync(0xffffffffu, mx0, 1));
        mx0 = fmaxf(mx0, __shfl_xor_sync(0xffffffffu, mx0, 2));
        mx1 = fmaxf(mx1, __shfl_xor_sync(0xffffffffu, mx1, 1));
        mx1 = fmaxf(mx1, __shfl_xor_sync(0xffffffffu, mx1, 2));
        float s0 = 0.f, s1 = 0.f;
        #pragma unroll
        for (int nt = 0; nt < 8; nt++) {
            sac[nt][0] = __expf(0.125f * (sac[nt][0] - mx0)); s0 += sac[nt][0];
            sac[nt][1] = __expf(0.125f * (sac[nt][1] - mx0)); s0 += sac[nt][1];
            sac[nt][2] = __expf(0.125f * (sac[nt][2] - mx1)); s1 += sac[nt][2];
            sac[nt][3] = __expf(0.125f * (sac[nt][3] - mx1)); s1 += sac[nt][3];
        }
        s0 += __shfl_xor_sync(0xffffffffu, s0, 1);
        s0 += __shfl_xor_sync(0xffffffffu, s0, 2);
        s1 += __shfl_xor_sync(0xffffffffu, s1, 1);
        s1 += __shfl_xor_sync(0xffffffffu, s1, 2);
        float i0 = 1.f / s0, i1 = 1.f / s1;
        #pragma unroll
        for (int nt = 0; nt < 8; nt++) {
            sac[nt][0] *= i0; sac[nt][1] *= i0;
            sac[nt][2] *= i1; sac[nt][3] *= i1;
        }
        float oac[8][4];
        zero8(oac);
        chain8_s(sac, vw, lane, oac);

        int t0 = tb + g, t1 = t0 + 8;
        int p0 = (t0 >> 3) * 16 + wx2 * 8 + (t0 & 7);
        int p1 = (t1 >> 3) * 16 + wx2 * 8 + (t1 & 7);
        #pragma unroll
        for (int nt = 0; nt < 8; nt++) {
            int ch = 8 * nt + 2 * tg;
            *(uint32_t*)(attnA + p0 * BP + ch) = pk(oac[nt][0], oac[nt][1]);
            *(uint32_t*)(attnA + p1 * BP + ch) = pk(oac[nt][2], oac[nt][3]);
        }
    }

    // ---- conv: warp w -> tile row w (no barrier needed: halo read-only) ----
    int py0 = wid;
    float cac[4][4];
    #pragma unroll
    for (int nt = 0; nt < 4; nt++)
        #pragma unroll
        for (int i = 0; i < 4; i++) cac[nt][i] = 0.f;

    #pragma unroll
    for (int tap = 0; tap < 9; tap++) {
        int ky = tap / 3, kx = tap - ky * 3;
        #pragma unroll
        for (int kt = 0; kt < 4; kt++) {
            uint2 bf[4];
            #pragma unroll
            for (int nt = 0; nt < 4; nt++)
                bf[nt] = __ldg(&g_w1f[tap * 512 + (kt * 4 + nt) * 32 + lane]);
            uint32_t af[4];
            ldsm4(af, s2u(halo + ((py0 + ky) * 18 + kx + lr + (quad & 1) * 8) * BP
                          + (quad >> 1) * 8 + 16 * kt));
            #pragma unroll
            for (int nt = 0; nt < 4; nt++)
                mma_bf16(cac[nt], af[0], af[1], af[2], af[3], bf[nt].x, bf[nt].y);
        }
    }
    #pragma unroll
    for (int nt = 0; nt < 4; nt++) {
        int ch = 8 * nt + 2 * tg;
        float bb0 = __ldg(&ms1_b[ch]), bb1 = __ldg(&ms1_b[ch + 1]);
        cac[nt][0] = fmaxf(cac[nt][0] + bb0, 0.f);
        cac[nt][1] = fmaxf(cac[nt][1] + bb1, 0.f);
        cac[nt][2] = fmaxf(cac[nt][2] + bb0, 0.f);
        cac[nt][3] = fmaxf(cac[nt][3] + bb1, 0.f);
    }
    float dac[8][4];
    bias8(dac, ms2_b, lane);
    #pragma unroll
    for (int kt = 0; kt < 2; kt++) {
        uint32_t a0 = pk(cac[2 * kt][0], cac[2 * kt][1]);
        uint32_t a1 = pk(cac[2 * kt][2], cac[2 * kt][3]);
        uint32_t a2 = pk(cac[2 * kt + 1][0], cac[2 * kt + 1][1]);
        uint32_t a3 = pk(cac[2 * kt + 1][2], cac[2 * kt + 1][3]);
        #pragma unroll
        for (int nt = 0; nt < 8; nt++) {
            uint2 bfr = __ldg(&g_w2f[(kt * 8 + nt) * 32 + lane]);
            mma_bf16(dac[nt], a0, a1, a2, a3, bfr.x, bfr.y);
        }
    }
    __syncthreads();   // all halo reads + attnA writes done; stage may overwrite

    {   // dac -> stage
        int p0 = py0 * 16 + g, p1 = p0 + 8;
        #pragma unroll
        for (int nt = 0; nt < 8; nt++) {
            int ch = 8 * nt + 2 * tg;
            stage[p0 * FP + ch]     = dac[nt][0];
            stage[p0 * FP + ch + 1] = dac[nt][1];
            stage[p1 * FP + ch]     = dac[nt][2];
            stage[p1 * FP + ch + 1] = dac[nt][3];
        }
    }
    __syncthreads();

    {   // + x (fp32 re-read, L2-warm) + attnA
        int p = tid >> 1, c0h = (tid & 1) * 32;
        int py = p >> 4, px = p & 15;
        const float* xp = x + (size_t)b * NC * PIX + (size_t)(gy0 + py) * HW + gx0 + px
                        + (size_t)c0h * PIX;
        #pragma unroll 8
        for (int c = 0; c < 32; c++)
            stage[p * FP + c0h + c] += xp[(size_t)c * PIX]
                                     + __bfloat162float(attnA[p * BP + c0h + c]);
    }
    __syncthreads();

    {   // LN: thread pair per pixel; tn overwrites attnA region (consumed above)
        int p = tid >> 1, c0h = (tid & 1) * 32;
        float s = 0.f;
        #pragma unroll 8
        for (int c = 0; c < 32; c++) s += stage[p * FP + c0h + c];
        s += __shfl_xor_sync(0xffffffffu, s, 1);
        float mu = s * (1.f / NC);
        float v = 0.f;
        #pragma unroll 8
        for (int c = 0; c < 32; c++) { float d = stage[p * FP + c0h + c] - mu; v += d * d; }
        v += __shfl_xor_sync(0xffffffffu, v, 1);
        float rs = rsqrtf(v * (1.f / NC) + 1e-5f);
        #pragma unroll 8
        for (int c = 0; c < 32; c++)
            tn[p * BP + c0h + c] = __float2bfloat16(
                (stage[p * FP + c0h + c] - mu) * rs * __ldg(&ln_g[c0h + c]) + __ldg(&ln_b[c0h + c]));
    }
    __syncthreads();

    // ---- FFN: 8 warps, 16 rows each ----
    {
        int R = wid * 16;
        uint32_t af[4][4];
        lda4(af, tn + R * BP, lane);
        float fac[8][4];
        bias8(fac, fc1_b, lane);
        gemm8_gf(af, g_f1f, lane, fac);
        #pragma unroll
        for (int nt = 0; nt < 8; nt++)
            #pragma unroll
            for (int i = 0; i < 4; i++) fac[nt][i] = gelu_f(fac[nt][i]);
        float gac[8][4];
        bias8(gac, fc2_b, lane);
        chain8_g(fac, g_f2f, lane, gac);

        int p0 = R + g, p1 = p0 + 8;
        int py0o = p0 >> 4, px0o = p0 & 15;
        int py1o = p1 >> 4, px1o = p1 & 15;
        #pragma unroll
        for (int nt = 0; nt < 8; nt++) {
            int ch = 8 * nt + 2 * tg;
            size_t o0 = ((size_t)(b * NC + ch)) * PIX;
            size_t o1 = ((size_t)(b * NC + ch + 1)) * PIX;
            out[o0 + (size_t)(gy0 + py0o) * HW + gx0 + px0o] = gac[nt][0] + stage[p0 * FP + ch];
            out[o1 + (size_t)(gy0 + py0o) * HW + gx0 + px0o] = gac[nt][1] + stage[p0 * FP + ch + 1];
            out[o0 + (size_t)(gy0 + py1o) * HW + gx0 + px1o] = gac[nt][2] + stage[p1 * FP + ch];
            out[o1 + (size_t)(gy0 + py1o) * HW + gx0 + px1o] = gac[nt][3] + stage[p1 * FP + ch + 1];
        }
    }
}

// ============================================================
extern "C" void kernel_launch(void* const* d_in, const int* in_sizes, int n_in,
                              void* d_out, int out_size) {
    const float* x     = (const float*)d_in[0];
    const float* qk_w  = (const float*)d_in[1];
    const float* qk_b  = (const float*)d_in[2];
    const float* v_w   = (const float*)d_in[3];
    const float* v_b   = (const float*)d_in[4];
    const float* out_w = (const float*)d_in[5];
    const float* out_b = (const float*)d_in[6];
    const float* ms1_w = (const float*)d_in[7];
    const float* ms1_b = (const float*)d_in[8];
    const float* ms2_w = (const float*)d_in[9];
    const float* ms2_b = (const float*)d_in[10];
    const float* se1_w = (const float*)d_in[11];
    const float* se1_b = (const float*)d_in[12];
    const float* se2_w = (const float*)d_in[13];
    const float* se2_b = (const float*)d_in[14];
    const float* ln_g  = (const float*)d_in[15];
    const float* ln_b  = (const float*)d_in[16];
    const float* fc1_w = (const float*)d_in[17];
    const float* fc1_b = (const float*)d_in[18];
    const float* fc2_w = (const float*)d_in[19];
    const float* fc2_b = (const float*)d_in[20];
    float* out = (float*)d_out;

    const int smem_mega = 33280 + 18432 + 512 + 18432;   // 70656 -> 2 CTAs/SM
    cudaFuncSetAttribute(k_mega, cudaFuncAttributeMaxDynamicSharedMemorySize, smem_mega);

    k_fold<<<16, 256>>>(qk_w, qk_b, out_w, v_w, v_b, out_b);
    k_prep_gap<<<24 + NB * NC * 4, 256>>>(fc1_w, fc2_w, ms1_w, ms2_w, x);
    k_gate<<<1, 512>>>(se1_w, se1_b, se2_w, se2_b);
    k_mega<<<dim3(16, 32, NB), 256, smem_mega>>>(x, ms1_b, ms2_b, ln_g, ln_b,
                                                 fc1_b, fc2_b, out);
}

// round 17
// speedup vs baseline: 1.1206x; 1.1206x over previous
#include <cuda_runtime.h>
#include <cuda_bf16.h>
#include <cstdint>
#include <stdint.h>
#include <math.h>

#define HW   256
#define PIX  65536
#define NB   8
#define NC   64
#define BP   72    // bf16 smem pitch
#define FP   65    // fp32 smem pitch
// column swizzle for FP-pitch fp32 tiles (conflict-free row-varying access)
#define SWC(p, c) (((c) + ((p) << 2)) & 63)

// ---- scratch ----
__device__ float g_gap[NB * NC];
__device__ float g_gate[NB * NC];
__device__ float g_wvo[4096];
__device__ float g_bvo[64];

// fragment-packed bf16 weights
__device__ __align__(16) uint2 g_wqf[1024];
__device__ __align__(16) uint2 g_wkf[1024];
__device__ __align__(16) uint2 g_wvof[1024];
__device__ __align__(16) uint2 g_f1f[1024];
__device__ __align__(16) uint2 g_f2f[1024];
__device__ __align__(16) uint2 g_w1f[9 * 512];
__device__ __align__(16) uint2 g_w2f[512];

// ============================================================
__device__ __forceinline__ void mma_bf16(float acc[4], uint32_t a0, uint32_t a1,
                                         uint32_t a2, uint32_t a3,
                                         uint32_t b0, uint32_t b1) {
    asm volatile(
        "mma.sync.aligned.m16n8k16.row.col.f32.bf16.bf16.f32 "
        "{%0,%1,%2,%3},{%4,%5,%6,%7},{%8,%9},{%0,%1,%2,%3};"
        : "+f"(acc[0]), "+f"(acc[1]), "+f"(acc[2]), "+f"(acc[3])
        : "r"(a0), "r"(a1), "r"(a2), "r"(a3), "r"(b0), "r"(b1));
}

__device__ __forceinline__ uint32_t pk(float x, float y) {
    __nv_bfloat162 h = __floats2bfloat162_rn(x, y);
    return *(uint32_t*)&h;
}

__device__ __forceinline__ uint32_t s2u(const void* p) {
    return (uint32_t)__cvta_generic_to_shared(p);
}

__device__ __forceinline__ void ldsm4(uint32_t r[4], uint32_t a) {
    asm volatile("ldmatrix.sync.aligned.m8n8.x4.shared.b16 {%0,%1,%2,%3}, [%4];"
                 : "=r"(r[0]), "=r"(r[1]), "=r"(r[2]), "=r"(r[3]) : "r"(a));
}

__device__ __forceinline__ void lda4(uint32_t af[4][4], const __nv_bfloat16* A, int lane) {
    int lr = lane & 7, quad = lane >> 3;
    const __nv_bfloat16* p = A + (lr + (quad & 1) * 8) * BP + (quad >> 1) * 8;
    #pragma unroll
    for (int kt = 0; kt < 4; kt++) ldsm4(af[kt], s2u(p + 16 * kt));
}

// A-frags = window tokens gathered from the 10x18 halo tile
__device__ __forceinline__ void lda4_win(uint32_t af[4][4], const __nv_bfloat16* halo,
                                         int wx2, int tb, int lane) {
    int lr = lane & 7, quad = lane >> 3;
    int token = tb + lr + (quad & 1) * 8;
    int ty = token >> 3, tx = token & 7;
    const __nv_bfloat16* p = halo + ((1 + ty) * 18 + 1 + wx2 * 8 + tx) * BP
                           + (quad >> 1) * 8;
    #pragma unroll
    for (int kt = 0; kt < 4; kt++) ldsm4(af[kt], s2u(p + 16 * kt));
}

__device__ __forceinline__ void gemm8_gf(const uint32_t af[4][4],
                                         const uint2* __restrict__ Bf,
                                         int lane, float acc[8][4]) {
    #pragma unroll
    for (int kt = 0; kt < 4; kt++)
        #pragma unroll
        for (int nt = 0; nt < 8; nt++) {
            uint2 b = __ldg(&Bf[(kt * 8 + nt) * 32 + lane]);
            mma_bf16(acc[nt], af[kt][0], af[kt][1], af[kt][2], af[kt][3], b.x, b.y);
        }
}

__device__ __forceinline__ void chain8_s(const float ca[8][4],
                                         const __nv_bfloat16* __restrict__ B,
                                         int lane, float acc[8][4]) {
    int lr = lane & 7, quad = lane >> 3;
    #pragma unroll
    for (int kt = 0; kt < 4; kt++) {
        uint32_t a0 = pk(ca[2 * kt][0], ca[2 * kt][1]);
        uint32_t a1 = pk(ca[2 * kt][2], ca[2 * kt][3]);
        uint32_t a2 = pk(ca[2 * kt + 1][0], ca[2 * kt + 1][1]);
        uint32_t a3 = pk(ca[2 * kt + 1][2], ca[2 * kt + 1][3]);
        #pragma unroll
        for (int p = 0; p < 4; p++) {
            uint32_t bf[4];
            ldsm4(bf, s2u(B + (16 * p + lr + (quad >> 1) * 8) * BP
                          + (quad & 1) * 8 + 16 * kt));
            mma_bf16(acc[2 * p],     a0, a1, a2, a3, bf[0], bf[1]);
            mma_bf16(acc[2 * p + 1], a0, a1, a2, a3, bf[2], bf[3]);
        }
    }
}

__device__ __forceinline__ void chain8_g(const float ca[8][4],
                                         const uint2* __restrict__ Bf,
                                         int lane, float acc[8][4]) {
    #pragma unroll
    for (int kt = 0; kt < 4; kt++) {
        uint32_t a0 = pk(ca[2 * kt][0], ca[2 * kt][1]);
        uint32_t a1 = pk(ca[2 * kt][2], ca[2 * kt][3]);
        uint32_t a2 = pk(ca[2 * kt + 1][0], ca[2 * kt + 1][1]);
        uint32_t a3 = pk(ca[2 * kt + 1][2], ca[2 * kt + 1][3]);
        #pragma unroll
        for (int nt = 0; nt < 8; nt++) {
            uint2 b = __ldg(&Bf[(kt * 8 + nt) * 32 + lane]);
            mma_bf16(acc[nt], a0, a1, a2, a3, b.x, b.y);
        }
    }
}

__device__ __forceinline__ void bias8(float acc[8][4], const float* __restrict__ b, int lane) {
    int tg = lane & 3;
    #pragma unroll
    for (int nt = 0; nt < 8; nt++) {
        float b0 = __ldg(b + 8 * nt + 2 * tg);
        float b1 = __ldg(b + 8 * nt + 2 * tg + 1);
        acc[nt][0] = b0; acc[nt][1] = b1; acc[nt][2] = b0; acc[nt][3] = b1;
    }
}

__device__ __forceinline__ void zero8(float acc[8][4]) {
    #pragma unroll
    for (int nt = 0; nt < 8; nt++)
        #pragma unroll
        for (int i = 0; i < 4; i++) acc[nt][i] = 0.f;
}

__device__ __forceinline__ void store8(__nv_bfloat16* __restrict__ D,
                                       const float acc[8][4], int lane) {
    int g = lane >> 2, tg = lane & 3;
    #pragma unroll
    for (int nt = 0; nt < 8; nt++) {
        int col = 8 * nt + 2 * tg;
        *(uint32_t*)(D + g * BP + col) = pk(acc[nt][0], acc[nt][1]);
        *(uint32_t*)(D + (g + 8) * BP + col) = pk(acc[nt][2], acc[nt][3]);
    }
}

// ============================================================
// K-1: fold out_w @ v_w; zero g_gap for the atomic GAP
// ============================================================
__global__ void k_fold(const float* __restrict__ out_w, const float* __restrict__ v_w,
                       const float* __restrict__ v_b, const float* __restrict__ out_b) {
    int idx = blockIdx.x * 256 + threadIdx.x;
    if (idx < 512) g_gap[idx] = 0.f;
    int o = idx >> 6, i = idx & 63;
    float s = 0.f;
    #pragma unroll 8
    for (int c = 0; c < 64; c++) s += out_w[o * 64 + c] * v_w[c * 64 + i];
    g_wvo[idx] = s;
    if (i == 0) {
        float bb = out_b[o];
        for (int c = 0; c < 64; c++) bb += out_w[o * 64 + c] * v_b[c];
        g_bvo[o] = bb;
    }
}

// ============================================================
// K0: combined weight-pack (blocks 0..23) + GAP (blocks 24..)
// ============================================================
__global__ void k_prep_gap(const float* __restrict__ qk_w, const float* __restrict__ fc1_w,
                           const float* __restrict__ fc2_w, const float* __restrict__ ms1_w,
                           const float* __restrict__ ms2_w, const float* __restrict__ x) {
    if (blockIdx.x >= 24) {
        int gb = blockIdx.x - 24;
        int bc = gb >> 2, part = gb & 3;
        const float4* p = (const float4*)(x + (size_t)bc * PIX) + part * 4096;
        float s = 0.f;
        #pragma unroll 4
        for (int i = threadIdx.x; i < 4096; i += 256) {
            float4 v = __ldg(&p[i]);
            s += v.x + v.y + v.z + v.w;
        }
        #pragma unroll
        for (int st = 16; st > 0; st >>= 1) s += __shfl_xor_sync(0xffffffffu, s, st);
        __shared__ float red[8];
        if ((threadIdx.x & 31) == 0) red[threadIdx.x >> 5] = s;
        __syncthreads();
        if (threadIdx.x == 0) {
            float t = 0.f;
            #pragma unroll
            for (int i = 0; i < 8; i++) t += red[i];
            atomicAdd(&g_gap[bc], t * (1.f / PIX));
        }
        return;
    }
    int n = 24 * 256;
    int t0 = blockIdx.x * 256 + threadIdx.x;
    for (int idx = t0; idx < 1024; idx += n) {
        int kt = idx >> 8, r = idx & 255;
        int nt = r >> 5, lane = r & 31;
        int g = lane >> 2, tg = lane & 3;
        int row = 8 * nt + g, col = 2 * tg + 16 * kt;
        #define PACK64(W) make_uint2(pk((W)[row * 64 + col], (W)[row * 64 + col + 1]), \
                                     pk((W)[row * 64 + col + 8], (W)[row * 64 + col + 9]))
        g_wqf[idx]  = PACK64(qk_w);
        g_wkf[idx]  = PACK64(qk_w + 4096);
        g_wvof[idx] = PACK64(g_wvo);
        g_f1f[idx]  = PACK64(fc1_w);
        g_f2f[idx]  = PACK64(fc2_w);
        #undef PACK64
    }
    for (int idx = t0; idx < 9 * 512; idx += n) {
        int tap = idx >> 9, r = idx & 511;
        int kt = r >> 7, r2 = r & 127;
        int nt = r2 >> 5, lane = r2 & 31;
        int g = lane >> 2, tg = lane & 3;
        int row = 8 * nt + g, col = 2 * tg + 16 * kt;
        uint2 u;
        u.x = pk(ms1_w[(row * 64 + col) * 9 + tap],     ms1_w[(row * 64 + col + 1) * 9 + tap]);
        u.y = pk(ms1_w[(row * 64 + col + 8) * 9 + tap], ms1_w[(row * 64 + col + 9) * 9 + tap]);
        g_w1f[idx] = u;
    }
    for (int idx = t0; idx < 512; idx += n) {
        int kt = idx >> 8, r = idx & 255;
        int nt = r >> 5, lane = r & 31;
        int g = lane >> 2, tg = lane & 3;
        int row = 8 * nt + g, col = 2 * tg + 16 * kt;
        uint2 u;
        u.x = pk(ms2_w[row * 32 + col],     ms2_w[row * 32 + col + 1]);
        u.y = pk(ms2_w[row * 32 + col + 8], ms2_w[row * 32 + col + 9]);
        g_w2f[idx] = u;
    }
}

__global__ void k_gate(const float* __restrict__ se1_w, const float* __restrict__ se1_b,
                       const float* __restrict__ se2_w, const float* __restrict__ se2_b) {
    __shared__ float se[NB][4];
    int tid = threadIdx.x;
    if (tid < 32) {
        int b = tid >> 2, j = tid & 3;
        float s = se1_b[j];
        for (int c = 0; c < NC; c++) s += g_gap[b * NC + c] * se1_w[j * NC + c];
        se[b][j] = fmaxf(s, 0.f);
    }
    __syncthreads();
    int b = tid >> 6, o = tid & 63;
    float s = se2_b[o];
    #pragma unroll
    for (int j = 0; j < 4; j++) s += se[b][j] * se2_w[o * 4 + j];
    g_gate[tid] = 1.f / (1.f + __expf(-s));
}

// ============================================================
// MEGA kernel, 8x16 tile (2 windows) per CTA, 256 threads,
// 2 CTAs/SM. Bank-conflict-fixed halo fill + swizzled fp32 tiles.
// ============================================================
__device__ __forceinline__ float gelu_f(float v) {
    float u = 0.7978845608028654f * (v + 0.044715f * v * v * v);
    return v / (1.f + __expf(-2.f * u));
}

__global__ void __launch_bounds__(256, 2) k_mega(
        const float* __restrict__ x, const float* __restrict__ qk_b,
        const float* __restrict__ v_b, const float* __restrict__ out_b_unused,
        const float* __restrict__ ms1_b, const float* __restrict__ ms2_b,
        const float* __restrict__ ln_g, const float* __restrict__ ln_b,
        const float* __restrict__ fc1_b, const float* __restrict__ fc2_b,
        float* __restrict__ out) {
    extern __shared__ char smc[];
    __nv_bfloat16* halo  = (__nv_bfloat16*)smc;            // [180][BP] = 25920B
    float*         stage = (float*)smc;                    // [128][FP] = 33280B (aliases halo)
    __nv_bfloat16* ks    = (__nv_bfloat16*)(smc + 33280);  // [128 tok][BP] = 18432B
    __nv_bfloat16* vT    = (__nv_bfloat16*)(smc + 51712);  // [2][64][BP]   = 18432B
    float*         attnO = (float*)(smc + 33280);          // [128][FP] (aliases ks+vT)
    __nv_bfloat16* tn    = (__nv_bfloat16*)(smc + 33280);  // aliases attnO

    int tid = threadIdx.x, lane = tid & 31, wid = tid >> 5;
    int g = lane >> 2, tg = lane & 3;
    int lr = lane & 7, quad = lane >> 3;
    int b = blockIdx.z;
    int gy0 = blockIdx.y << 3, gx0 = blockIdx.x << 4;

    // ---- halo load: 2 channels/thread, uint32 smem stores (half the
    // conflicted wavefronts of the scalar STS.16 version) ----
    for (int idx = tid; idx < 5760; idx += 256) {
        int cp = idx / 180, r = idx - cp * 180;   // cp = channel pair
        int hy = r / 18, hx = r - hy * 18;
        int gy = gy0 + hy - 1, gx = gx0 + hx - 1;
        float v0 = 0.f, v1 = 0.f;
        if (gy >= 0 && gy < HW && gx >= 0 && gx < HW) {
            const float* xp = x + ((size_t)(b * NC + 2 * cp)) * PIX + (size_t)gy * HW + gx;
            v0 = xp[0];
            v1 = xp[PIX];
        }
        *(uint32_t*)(halo + r * BP + 2 * cp) = pk(v0, v1);
    }
    __syncthreads();

    // ---- attention: warp w -> window w>>2 (wx2), quarter w&3 ----
    int wx2 = wid >> 2, q4 = wid & 3;
    int tb = q4 * 16;
    __nv_bfloat16* vw = vT + wx2 * 64 * BP;

    {   // K proj + gated VO proj
        uint32_t af[4][4];
        lda4_win(af, halo, wx2, tb, lane);
        float acc[8][4];
        bias8(acc, qk_b + 64, lane);
        gemm8_gf(af, g_wkf, lane, acc);
        store8(ks + (wx2 * 64 + tb) * BP, acc, lane);

        bias8(acc, g_bvo, lane);
        gemm8_gf(af, g_wvof, lane, acc);
        int tI = tb + g;
        #pragma unroll
        for (int nt = 0; nt < 8; nt++) {
            int ch = 8 * nt + 2 * tg;
            float ga0 = __ldg(&g_gate[b * NC + ch]);
            float ga1 = __ldg(&g_gate[b * NC + ch + 1]);
            vw[ch * BP + tI]           = __float2bfloat16(acc[nt][0] * ga0);
            vw[(ch + 1) * BP + tI]     = __float2bfloat16(acc[nt][1] * ga1);
            vw[ch * BP + tI + 8]       = __float2bfloat16(acc[nt][2] * ga0);
            vw[(ch + 1) * BP + tI + 8] = __float2bfloat16(acc[nt][3] * ga1);
        }
    }
    __syncthreads();

    float oac[8][4];
    {   // Q proj, scores, softmax, P@u
        uint32_t af[4][4];
        lda4_win(af, halo, wx2, tb, lane);
        float qac[8][4];
        bias8(qac, qk_b, lane);
        gemm8_gf(af, g_wqf, lane, qac);

        float sac[8][4];
        zero8(sac);
        chain8_s(qac, ks + wx2 * 64 * BP, lane, sac);

        float mx0 = -1e30f, mx1 = -1e30f;
        #pragma unroll
        for (int nt = 0; nt < 8; nt++) {
            mx0 = fmaxf(mx0, fmaxf(sac[nt][0], sac[nt][1]));
            mx1 = fmaxf(mx1, fmaxf(sac[nt][2], sac[nt][3]));
        }
        mx0 = fmaxf(mx0, __shfl_xor_sync(0xffffffffu, mx0, 1));
        mx0 = fmaxf(mx0, __shfl_xor_sync(0xffffffffu, mx0, 2));
        mx1 = fmaxf(mx1, __shfl_xor_sync(0xffffffffu, mx1, 1));
        mx1 = fmaxf(mx1, __shfl_xor_sync(0xffffffffu, mx1, 2));
        float s0 = 0.f, s1 = 0.f;
        #pragma unroll
        for (int nt = 0; nt < 8; nt++) {
            sac[nt][0] = __expf(0.125f * (sac[nt][0] - mx0)); s0 += sac[nt][0];
            sac[nt][1] = __expf(0.125f * (sac[nt][1] - mx0)); s0 += sac[nt][1];
            sac[nt][2] = __expf(0.125f * (sac[nt][2] - mx1)); s1 += sac[nt][2];
            sac[nt][3] = __expf(0.125f * (sac[nt][3] - mx1)); s1 += sac[nt][3];
        }
        s0 += __shfl_xor_sync(0xffffffffu, s0, 1);
        s0 += __shfl_xor_sync(0xffffffffu, s0, 2);
        s1 += __shfl_xor_sync(0xffffffffu, s1, 1);
        s1 += __shfl_xor_sync(0xffffffffu, s1, 2);
        float i0 = 1.f / s0, i1 = 1.f / s1;
        #pragma unroll
        for (int nt = 0; nt < 8; nt++) {
            sac[nt][0] *= i0; sac[nt][1] *= i0;
            sac[nt][2] *= i1; sac[nt][3] *= i1;
        }
        zero8(oac);
        chain8_s(sac, vw, lane, oac);
    }
    __syncthreads();   // ks/vT reads done

    {   // attention out -> attnO (fp32, swizzled columns)
        int t0 = tb + g, t1 = t0 + 8;
        int p0 = (t0 >> 3) * 16 + wx2 * 8 + (t0 & 7);
        int p1 = (t1 >> 3) * 16 + wx2 * 8 + (t1 & 7);
        #pragma unroll
        for (int nt = 0; nt < 8; nt++) {
            int ch = 8 * nt + 2 * tg;
            attnO[p0 * FP + SWC(p0, ch)]     = oac[nt][0];
            attnO[p0 * FP + SWC(p0, ch + 1)] = oac[nt][1];
            attnO[p1 * FP + SWC(p1, ch)]     = oac[nt][2];
            attnO[p1 * FP + SWC(p1, ch + 1)] = oac[nt][3];
        }
    }

    // ---- conv: warp w -> tile row w ----
    int py0 = wid;
    float cac[4][4];
    #pragma unroll
    for (int nt = 0; nt < 4; nt++)
        #pragma unroll
        for (int i = 0; i < 4; i++) cac[nt][i] = 0.f;

    #pragma unroll
    for (int tap = 0; tap < 9; tap++) {
        int ky = tap / 3, kx = tap - ky * 3;
        #pragma unroll
        for (int kt = 0; kt < 4; kt++) {
            uint2 bf[4];
            #pragma unroll
            for (int nt = 0; nt < 4; nt++)
                bf[nt] = __ldg(&g_w1f[tap * 512 + (kt * 4 + nt) * 32 + lane]);
            uint32_t af[4];
            ldsm4(af, s2u(halo + ((py0 + ky) * 18 + kx + lr + (quad & 1) * 8) * BP
                          + (quad >> 1) * 8 + 16 * kt));
            #pragma unroll
            for (int nt = 0; nt < 4; nt++)
                mma_bf16(cac[nt], af[0], af[1], af[2], af[3], bf[nt].x, bf[nt].y);
        }
    }
    #pragma unroll
    for (int nt = 0; nt < 4; nt++) {
        int ch = 8 * nt + 2 * tg;
        float bb0 = __ldg(&ms1_b[ch]), bb1 = __ldg(&ms1_b[ch + 1]);
        cac[nt][0] = fmaxf(cac[nt][0] + bb0, 0.f);
        cac[nt][1] = fmaxf(cac[nt][1] + bb1, 0.f);
        cac[nt][2] = fmaxf(cac[nt][2] + bb0, 0.f);
        cac[nt][3] = fmaxf(cac[nt][3] + bb1, 0.f);
    }
    float dac[8][4];
    bias8(dac, ms2_b, lane);
    #pragma unroll
    for (int kt = 0; kt < 2; kt++) {
        uint32_t a0 = pk(cac[2 * kt][0], cac[2 * kt][1]);
        uint32_t a1 = pk(cac[2 * kt][2], cac[2 * kt][3]);
        uint32_t a2 = pk(cac[2 * kt + 1][0], cac[2 * kt + 1][1]);
        uint32_t a3 = pk(cac[2 * kt + 1][2], cac[2 * kt + 1][3]);
        #pragma unroll
        for (int nt = 0; nt < 8; nt++) {
            uint2 bfr = __ldg(&g_w2f[(kt * 8 + nt) * 32 + lane]);
            mma_bf16(dac[nt], a0, a1, a2, a3, bfr.x, bfr.y);
        }
    }
    __syncthreads();   // halo reads done; stage may overwrite

    {   // dac -> stage (swizzled, conflict-free per instruction)
        int p0 = py0 * 16 + g, p1 = p0 + 8;
        #pragma unroll
        for (int nt = 0; nt < 8; nt++) {
            int ch = 8 * nt + 2 * tg;
            stage[p0 * FP + SWC(p0, ch)]     = dac[nt][0];
            stage[p0 * FP + SWC(p0, ch + 1)] = dac[nt][1];
            stage[p1 * FP + SWC(p1, ch)]     = dac[nt][2];
            stage[p1 * FP + SWC(p1, ch + 1)] = dac[nt][3];
        }
    }
    __syncthreads();

    {   // + x (fp32 re-read, L2-warm) + attnO
        int p = tid >> 1, c0h = (tid & 1) * 32;
        int py = p >> 4, px = p & 15;
        const float* xp = x + (size_t)b * NC * PIX + (size_t)(gy0 + py) * HW + gx0 + px
                        + (size_t)c0h * PIX;
        #pragma unroll 8
        for (int c = 0; c < 32; c++) {
            int col = SWC(p, c0h + c);
            stage[p * FP + col] += xp[(size_t)c * PIX] + attnO[p * FP + col];
        }
    }
    __syncthreads();

    {   // LN: thread pair per pixel
        int p = tid >> 1, c0h = (tid & 1) * 32;
        float s = 0.f;
        #pragma unroll 8
        for (int c = 0; c < 32; c++) s += stage[p * FP + SWC(p, c0h + c)];
        s += __shfl_xor_sync(0xffffffffu, s, 1);
        float mu = s * (1.f / NC);
        float v = 0.f;
        #pragma unroll 8
        for (int c = 0; c < 32; c++) {
            float d = stage[p * FP + SWC(p, c0h + c)] - mu;
            v += d * d;
        }
        v += __shfl_xor_sync(0xffffffffu, v, 1);
        float rs = rsqrtf(v * (1.f / NC) + 1e-5f);
        #pragma unroll 8
        for (int c = 0; c < 32; c++) {
            int cc = c0h + c;
            tn[p * BP + cc] = __float2bfloat16(
                (stage[p * FP + SWC(p, cc)] - mu) * rs * __ldg(&ln_g[cc]) + __ldg(&ln_b[cc]));
        }
    }
    __syncthreads();

    // ---- FFN: 8 warps, 16 rows each ----
    {
        int R = wid * 16;
        uint32_t af[4][4];
        lda4(af, tn + R * BP, lane);
        float fac[8][4];
        bias8(fac, fc1_b, lane);
        gemm8_gf(af, g_f1f, lane, fac);
        #pragma unroll
        for (int nt = 0; nt < 8; nt++)
            #pragma unroll
            for (int i = 0; i < 4; i++) fac[nt][i] = gelu_f(fac[nt][i]);
        float gac[8][4];
        bias8(gac, fc2_b, lane);
        chain8_g(fac, g_f2f, lane, gac);

        int p0 = R + g, p1 = p0 + 8;
        int py0o = p0 >> 4, px0o = p0 & 15;
        int py1o = p1 >> 4, px1o = p1 & 15;
        #pragma unroll
        for (int nt = 0; nt < 8; nt++) {
            int ch = 8 * nt + 2 * tg;
            size_t o0 = ((size_t)(b * NC + ch)) * PIX;
            size_t o1 = ((size_t)(b * NC + ch + 1)) * PIX;
            out[o0 + (size_t)(gy0 + py0o) * HW + gx0 + px0o] = gac[nt][0] + stage[p0 * FP + SWC(p0, ch)];
            out[o1 + (size_t)(gy0 + py0o) * HW + gx0 + px0o] = gac[nt][1] + stage[p0 * FP + SWC(p0, ch + 1)];
            out[o0 + (size_t)(gy0 + py1o) * HW + gx0 + px1o] = gac[nt][2] + stage[p1 * FP + SWC(p1, ch)];
            out[o1 + (size_t)(gy0 + py1o) * HW + gx0 + px1o] = gac[nt][3] + stage[p1 * FP + SWC(p1, ch + 1)];
        }
    }
}

// ============================================================
extern "C" void kernel_launch(void* const* d_in, const int* in_sizes, int n_in,
                              void* d_out, int out_size) {
    const float* x     = (const float*)d_in[0];
    const float* qk_w  = (const float*)d_in[1];
    const float* qk_b  = (const float*)d_in[2];
    const float* v_w   = (const float*)d_in[3];
    const float* v_b   = (const float*)d_in[4];
    const float* out_w = (const float*)d_in[5];
    const float* out_b = (const float*)d_in[6];
    const float* ms1_w = (const float*)d_in[7];
    const float* ms1_b = (const float*)d_in[8];
    const float* ms2_w = (const float*)d_in[9];
    const float* ms2_b = (const float*)d_in[10];
    const float* se1_w = (const float*)d_in[11];
    const float* se1_b = (const float*)d_in[12];
    const float* se2_w = (const float*)d_in[13];
    const float* se2_b = (const float*)d_in[14];
    const float* ln_g  = (const float*)d_in[15];
    const float* ln_b  = (const float*)d_in[16];
    const float* fc1_w = (const float*)d_in[17];
    const float* fc1_b = (const float*)d_in[18];
    const float* fc2_w = (const float*)d_in[19];
    const float* fc2_b = (const float*)d_in[20];
    float* out = (float*)d_out;

    const int smem_mega = 33280 + 18432 + 18432;   // 70144 -> 2 CTAs/SM, big L1D carveout
    cudaFuncSetAttribute(k_mega, cudaFuncAttributeMaxDynamicSharedMemorySize, smem_mega);

    k_fold<<<16, 256>>>(out_w, v_w, v_b, out_b);
    k_prep_gap<<<24 + NB * NC * 4, 256>>>(qk_w, fc1_w, fc2_w, ms1_w, ms2_w, x);
    k_gate<<<1, 512>>>(se1_w, se1_b, se2_w, se2_b);
    k_mega<<<dim3(16, 32, NB), 256, smem_mega>>>(x, qk_b, v_b, out_b, ms1_b, ms2_b,
                                                 ln_g, ln_b, fc1_b, fc2_b, out);
}